// round 12
// baseline (speedup 1.0000x reference)
#include <cuda_runtime.h>
#include <cuda_bf16.h>
#include <cstdint>

// ---------------------------------------------------------------------------
// OnlineLSTM, fully fused persistent kernel:
//   - 2048 sequential LSTM steps, W_hh in REGISTERS, counter grid barrier
//     (round-11 proven machinery, untouched)
//   - xg = inp @ W_ih^T computed INSIDE the recurrence's idle time:
//     each CTA produces its own 32 xg columns for step-block b+2 while
//     stepping through block b (one 32-wide K-chunk per step). CTA-local
//     only: no new inter-CTA sync, deadlock impossible.
//   - out = tanh(h_fin @ fc_w^T + fc_b); h_last/c_last at step 1023
// ---------------------------------------------------------------------------

#define WINDOW  2048
#define ISZ     4096
#define HID     1024
#define GATE4   4096      // 4*HID
#define METRIC  32
#define NCTA    128       // persistent CTAs
#define UPB     8         // hidden units per CTA (NCTA*UPB = HID)
#define BLK     128       // steps per xg block
#define KC      32        // K-chunk per step (BLK*KC = ISZ)

// Scratch (no cudaMalloc allowed)
__device__ float g_h[2][HID];
__device__ int   g_cnt;                          // monotonic barrier counter

// ===========================================================================
__device__ __forceinline__ void fma2(unsigned long long& acc,
                                     unsigned long long a,
                                     unsigned long long b) {
    asm("fma.rn.f32x2 %0, %1, %2, %0;" : "+l"(acc) : "l"(a), "l"(b));
}
__device__ __forceinline__ void red_release_add1(int* p) {
    asm volatile("red.release.gpu.global.add.s32 [%0], 1;" :: "l"(p) : "memory");
}
__device__ __forceinline__ int ld_acquire(const int* p) {
    int v;
    asm volatile("ld.acquire.gpu.global.b32 %0, [%1];" : "=r"(v) : "l"(p) : "memory");
    return v;
}
__device__ __forceinline__ float sig_exact(float x) {
    return 1.0f / (1.0f + __expf(-x));
}

// ===========================================================================
// Init: reset barrier counter, seed h buffer with h1 (round-3/11 verbatim)
// ===========================================================================
__global__ void init_kernel(const float* __restrict__ h1) {
    int i = threadIdx.x;   // 1024 threads
    if (i == 0) g_cnt = 0;
    g_h[0][i] = h1[i];
}

// ===========================================================================
// Persistent fused kernel. 128 CTAs x 512 threads.
//
// Recurrence (proven round-11 core):
//   Lane l of every warp owns gate-row r(l) = (l&3)*HID + bid*8 + (l>>2).
//   Warp w (0..15) owns h-columns [64w, 64w+64): 32 f32x2 W_hh regs.
//   Warp 0 reduces 16 per-warp partials, does gates, stores h; counter
//   barrier (release-RED + acquire poll) between steps.
//
// Inline xg producer:
//   Thread (w,l) accumulates xgblk[t'=8w+i][col=l] for i in 0..7 over the
//   K-chunk [ (t%128)*32, +32 ) of block tb = t/128 + 2, reading
//   inp[tb*128 + t'][k] (SMEM-staged, broadcast LDS) and W_ih[r(l)][k]
//   (LDG, L1-shared across the 16 warps). Dump at block end into
//   xgbuf[tb&1]; warp 0 reads xgbuf[(t/128)&1][(t%128)*32 + l] via LDS.
//   Slice work sits between barrier arrival (RED) and the poll, filling
//   otherwise-idle cycles. Prologue computes blocks 0 and 1.
// ===========================================================================
__global__ void __launch_bounds__(512, 1) lstm_fused_kernel(
    const float* __restrict__ inp,    // [2048,4096]
    const float* __restrict__ W_ih,   // [4096,4096]
    const float* __restrict__ W_hh,   // [4096,1024]
    const float* __restrict__ c1,     // [1024]
    const float* __restrict__ b_ih,   // [4096]
    const float* __restrict__ b_hh,   // [4096]
    float* __restrict__ out,          // d_out
    int writeHC)
{
    __shared__ __align__(16) float hsm[HID];
    __shared__ float psum[16][33];
    __shared__ __align__(16) float xgbuf[2][BLK * 32];   // 2 x 16KB
    __shared__ __align__(16) float inps[BLK][KC];        // 16KB staged inp chunk

    const int tid = threadIdx.x;
    const int bid = blockIdx.x;
    const int w = tid >> 5;            // warp 0..15
    const int l = tid & 31;            // lane
    const int u = l >> 2;
    const int g = l & 3;
    const int gate_row = g * HID + bid * UPB + u;   // this lane's W row (both W_hh and W_ih)

    // ---- W_hh slab into registers: 32 f32x2 (64 floats) per thread ----
    unsigned long long wreg[32];
    {
        const float* wp = W_hh + (size_t)gate_row * HID + w * 64;
#pragma unroll
        for (int k = 0; k < 32; k++)
            wreg[k] = *(const unsigned long long*)(wp + 2 * k);
    }

    // ---- warp-0 per-lane state: bias (b_hh + b_ih), c (g==0 lanes) ----
    float bias = 0.f, c = 0.f;
    if (w == 0) {
        bias = b_hh[gate_row] + b_ih[gate_row];
        if (g == 0) c = c1[bid * UPB + u];
    }

    const float* Wrow = W_ih + (size_t)gate_row * ISZ;   // this lane's W_ih row
    float acc[8];

    // ---------------- xg slice helpers (inlined via lambdas) ----------------
    // stage inp[t0 .. t0+128)[k0 .. k0+32) into inps: 16KB, 8 float4/thread
    auto stage_inp = [&](int t0, int k0) {
        const int r = tid >> 3;            // 0..63 (two passes of 64 rows)
        const int f4 = tid & 7;            // float4 within the 32-col chunk
        const float4* s0 = (const float4*)(inp + (size_t)(t0 + r) * ISZ + k0) + f4;
        const float4* s1 = (const float4*)(inp + (size_t)(t0 + 64 + r) * ISZ + k0) + f4;
        ((float4*)&inps[r][0])[f4]      = __ldg(s0);
        ((float4*)&inps[64 + r][0])[f4] = __ldg(s1);
    };
    // accumulate this K-chunk: thread (w,l): 8 t' x 32 k
    auto accum_chunk = [&](int k0) {
        float4 wv[8];
        const float4* wp4 = (const float4*)(Wrow + k0);
#pragma unroll
        for (int q = 0; q < 8; q++) wv[q] = __ldg(wp4 + q);
#pragma unroll
        for (int i = 0; i < 8; i++) {
            const float4* ip4 = (const float4*)&inps[8 * w + i][0];
            float s = 0.f;
#pragma unroll
            for (int q = 0; q < 8; q++) {
                float4 iv = ip4[q];
                s += wv[q].x * iv.x + wv[q].y * iv.y
                   + wv[q].z * iv.z + wv[q].w * iv.w;
            }
            acc[i] += s;
        }
    };
    auto dump_block = [&](int tb) {
        float* dst = &xgbuf[tb & 1][0];
#pragma unroll
        for (int i = 0; i < 8; i++) dst[(8 * w + i) * 32 + l] = acc[i];
#pragma unroll
        for (int i = 0; i < 8; i++) acc[i] = 0.f;
    };

    // ---------------- prologue: compute xg blocks 0 and 1 ----------------
#pragma unroll
    for (int i = 0; i < 8; i++) acc[i] = 0.f;
    for (int blk = 0; blk < 2; blk++) {
        for (int ch = 0; ch < BLK; ch++) {
            __syncthreads();                    // inps reuse guard
            stage_inp(blk * BLK, ch * KC);
            __syncthreads();
            accum_chunk(ch * KC);
        }
        __syncthreads();
        dump_block(blk);
    }
    __syncthreads();

    // ---------------- main loop: 2048 steps ----------------
    for (int t = 0; t < WINDOW; t++) {
        const int p = t & 1;

        // ---- broadcast h into SMEM (L2-only loads; proven pattern) ----
        if (tid < 256)
            ((float4*)hsm)[tid] = __ldcg(((const float4*)g_h[p]) + tid);
        __syncthreads();

        // ---- recurrence compute: 64-col partial dot via broadcast LDS ----
        unsigned long long racc = 0ull;
        const unsigned long long* hp = (const unsigned long long*)(hsm + w * 64);
#pragma unroll
        for (int k = 0; k < 32; k++) fma2(racc, wreg[k], hp[k]);
        {
            unsigned int lo, hi;
            asm("mov.b64 {%0, %1}, %2;" : "=r"(lo), "=r"(hi) : "l"(racc));
            psum[w][l] = __uint_as_float(lo) + __uint_as_float(hi);
        }
        __syncthreads();

        // ---- warp 0: reduce, gates, h store (round-11 verbatim math) ----
        if (w == 0) {
            float pre = xgbuf[(t >> 7) & 1][(t & 127) * 32 + l] + bias;
#pragma unroll
            for (int q = 0; q < 16; q++) pre += psum[q][l];

            float a = (g == 2) ? tanhf(pre) : sig_exact(pre);
            int base = l & ~3;
            float fg = __shfl_sync(0xffffffffu, a, base + 1);
            float gb = __shfl_sync(0xffffffffu, a, base + 2);
            float og = __shfl_sync(0xffffffffu, a, base + 3);
            if (g == 0) {
                c = fg * c + a * gb;
                float hn = og * tanhf(c);
                int jj = bid * UPB + u;
                g_h[p ^ 1][jj] = hn;
                if (writeHC && t == 1023) {          // STRIDE-1
                    out[METRIC + jj] = hn;
                    out[METRIC + HID + jj] = c;
                }
            }
        }
        __syncthreads();
        // NOTE: warp0's xgbuf read for step t is complete before any dump
        // below (separated by the __syncthreads above).

        // ---- barrier arrival (early), then xg slice in the idle window ----
        if (tid == 0) red_release_add1(&g_cnt);

        if (t < (16 - 2) * BLK) {                 // producing blocks 2..15
            const int tb = (t >> 7) + 2;
            const int k0 = (t & 127) * KC;
            stage_inp(tb * BLK, k0);
            __syncthreads();
            accum_chunk(k0);
            if ((t & 127) == 127) {
                __syncthreads();                  // all reads of old buf done
                dump_block(tb);
            }
        }

        // ---- barrier wait ----
        if (tid == 0) {
            const int target = (t + 1) * NCTA;
            while (ld_acquire(&g_cnt) < target) { }
        }
        __syncthreads();
    }
}

// ===========================================================================
// out = tanh(h_fin @ fc_w^T + fc_b). h_fin = g_h[0] (2048 even steps).
// ===========================================================================
__global__ void fc_kernel(const float* __restrict__ fc_w,
                          const float* __restrict__ fc_b,
                          float* __restrict__ out)
{
    const int w = threadIdx.x >> 5;    // 0..31 metric
    const int l = threadIdx.x & 31;
    const float* wv = fc_w + (size_t)w * HID;
    float s = 0.f;
#pragma unroll
    for (int jj = 0; jj < 8; jj++) {
        float4 a = __ldcg(((const float4*)g_h[0]) + l + 32 * jj);
        float4 b = ((const float4*)wv)[l + 32 * jj];
        s += a.x * b.x + a.y * b.y + a.z * b.z + a.w * b.w;
    }
#pragma unroll
    for (int off = 16; off; off >>= 1) s += __shfl_xor_sync(0xffffffffu, s, off);
    if (l == 0) out[w] = tanhf(s + fc_b[w]);
}

// ===========================================================================
// launch
// ===========================================================================
extern "C" void kernel_launch(void* const* d_in, const int* in_sizes, int n_in,
                              void* d_out, int out_size) {
    const float* inp  = (const float*)d_in[0];
    const float* h1   = (const float*)d_in[1];
    const float* c1   = (const float*)d_in[2];
    const float* W_ih = (const float*)d_in[3];
    const float* W_hh = (const float*)d_in[4];
    const float* b_ih = (const float*)d_in[5];
    const float* b_hh = (const float*)d_in[6];
    const float* fc_w = (const float*)d_in[7];
    const float* fc_b = (const float*)d_in[8];
    float* out = (float*)d_out;

    int writeHC = (out_size >= METRIC + 2 * HID) ? 1 : 0;

    // Phase 1: init h buffer + barrier counter
    init_kernel<<<1, HID>>>(h1);

    // Phase 2: fused persistent recurrence + inline xg producer
    lstm_fused_kernel<<<NCTA, 512>>>(inp, W_ih, W_hh, c1, b_ih, b_hh,
                                     out, writeHC);

    // Phase 3: fc epilogue
    fc_kernel<<<1, METRIC * 32>>>(fc_w, fc_b, out);
}

// round 13
// speedup vs baseline: 1.1692x; 1.1692x over previous
#include <cuda_runtime.h>
#include <cuda_bf16.h>
#include <cstdint>

// ---------------------------------------------------------------------------
// OnlineLSTM (round 13 = round 11 base + serial-chain trims):
//   Phase 1: xg = inp @ W_ih^T + b_ih  (proven FFMA2 SGEMM, unchanged)
//   Phase 2: persistent recurrence, W_hh in registers, counter barrier
//            (proven machinery) with: fast saturating activations,
//            4-accumulator dot, tree psum reduce, fc folded into tail.
//   3 launches/call -> ncu (-s 5 -c 1) captures lstm_rec_kernel.
// ---------------------------------------------------------------------------

#define WINDOW  2048
#define ISZ     4096
#define HID     1024
#define GATE4   4096      // 4*HID
#define METRIC  32
#define NCTA    128       // persistent CTAs
#define UPB     8         // hidden units per CTA (NCTA*UPB = HID)

// Scratch (no cudaMalloc allowed)
__device__ float g_xg[WINDOW * GATE4];          // 32 MB
__device__ float g_h[2][HID];
__device__ int   g_cnt;                          // monotonic barrier counter

// ===========================================================================
// GEMM: C[t][r] = sum_k inp[t][k] * W_ih[r][k] + b_ih[r]   (round-3 verbatim)
// ===========================================================================
#define BM 128
#define BN 128
#define BK 8
#define LDT (BM + 4)

__device__ __forceinline__ unsigned long long dup_f32x2(float a) {
    unsigned long long r;
    unsigned int ai = __float_as_uint(a);
    asm("mov.b64 %0, {%1, %1};" : "=l"(r) : "r"(ai));
    return r;
}
__device__ __forceinline__ void fma2(unsigned long long& acc,
                                     unsigned long long a,
                                     unsigned long long b) {
    asm("fma.rn.f32x2 %0, %1, %2, %0;" : "+l"(acc) : "l"(a), "l"(b));
}

__global__ void __launch_bounds__(256, 2) gemm_xg_kernel(
    const float* __restrict__ A,      // inp [2048,4096]
    const float* __restrict__ B,      // W_ih [4096,4096]
    const float* __restrict__ bias,   // b_ih [4096]
    float* __restrict__ C)            // g_xg [2048,4096]
{
    __shared__ __align__(16) float As[BK][LDT];
    __shared__ __align__(16) float Bs[BK][LDT];

    const int tid = threadIdx.x;
    const int bm = blockIdx.y * BM;
    const int bn = blockIdx.x * BN;

    const int lr = tid >> 1;
    const int lk = (tid & 1) * 4;
    const float* Aptr = A + (size_t)(bm + lr) * ISZ + lk;
    const float* Bptr = B + (size_t)(bn + lr) * ISZ + lk;

    const int tx = tid & 15;
    const int ty = tid >> 4;

    unsigned long long acc2[8][4];
#pragma unroll
    for (int i = 0; i < 8; i++)
#pragma unroll
        for (int j = 0; j < 4; j++) acc2[i][j] = 0ull;

    float4 av = *(const float4*)(Aptr);
    float4 bv = *(const float4*)(Bptr);

    for (int k0 = 0; k0 < ISZ; k0 += BK) {
        __syncthreads();
        As[lk + 0][lr] = av.x; As[lk + 1][lr] = av.y;
        As[lk + 2][lr] = av.z; As[lk + 3][lr] = av.w;
        Bs[lk + 0][lr] = bv.x; Bs[lk + 1][lr] = bv.y;
        Bs[lk + 2][lr] = bv.z; Bs[lk + 3][lr] = bv.w;
        __syncthreads();

        if (k0 + BK < ISZ) {
            av = *(const float4*)(Aptr + k0 + BK);
            bv = *(const float4*)(Bptr + k0 + BK);
        }

#pragma unroll
        for (int kk = 0; kk < BK; kk++) {
            float4 a0 = *(const float4*)&As[kk][ty * 8];
            float4 a1 = *(const float4*)&As[kk][ty * 8 + 4];
            ulonglong2 bq0 = *(const ulonglong2*)&Bs[kk][tx * 8];
            ulonglong2 bq1 = *(const ulonglong2*)&Bs[kk][tx * 8 + 4];
            unsigned long long b2[4] = {bq0.x, bq0.y, bq1.x, bq1.y};
            float a[8] = {a0.x, a0.y, a0.z, a0.w, a1.x, a1.y, a1.z, a1.w};
#pragma unroll
            for (int i = 0; i < 8; i++) {
                unsigned long long ad = dup_f32x2(a[i]);
#pragma unroll
                for (int j = 0; j < 4; j++) fma2(acc2[i][j], ad, b2[j]);
            }
        }
    }

    float bcol[8];
#pragma unroll
    for (int j = 0; j < 8; j++) bcol[j] = bias[bn + tx * 8 + j];

#pragma unroll
    for (int i = 0; i < 8; i++) {
        float* crow = C + (size_t)(bm + ty * 8 + i) * GATE4 + bn + tx * 8;
#pragma unroll
        for (int j = 0; j < 4; j++) {
            unsigned int lo, hi;
            asm("mov.b64 {%0, %1}, %2;" : "=r"(lo), "=r"(hi) : "l"(acc2[i][j]));
            crow[2 * j]     = __uint_as_float(lo) + bcol[2 * j];
            crow[2 * j + 1] = __uint_as_float(hi) + bcol[2 * j + 1];
        }
    }
}

// ===========================================================================
// Init: reset barrier counter, seed h buffer (proven)
// ===========================================================================
__global__ void init_kernel(const float* __restrict__ h1) {
    int i = threadIdx.x;   // 1024 threads
    if (i == 0) g_cnt = 0;
    g_h[0][i] = h1[i];
}

// ===========================================================================
// Barrier primitives (proven)
// ===========================================================================
__device__ __forceinline__ void red_release_add1(int* p) {
    asm volatile("red.release.gpu.global.add.s32 [%0], 1;" :: "l"(p) : "memory");
}
__device__ __forceinline__ int ld_acquire(const int* p) {
    int v;
    asm volatile("ld.acquire.gpu.global.b32 %0, [%1];" : "=r"(v) : "l"(p) : "memory");
    return v;
}

// Fast saturating activations (exact at +-inf; rel err ~1e-6)
__device__ __forceinline__ float sig_fast(float x) {
    return __fdividef(1.0f, 1.0f + __expf(-x));
}
__device__ __forceinline__ float tanh_fast(float x) {
    return 1.0f - __fdividef(2.0f, __expf(2.0f * x) + 1.0f);
}

// ===========================================================================
// Persistent LSTM recurrence (round-11 proven structure + chain trims).
//   128 CTAs x 512 threads; lane l owns gate-row (l&3)*HID + bid*8 + (l>>2);
//   warp w owns h-columns [64w,64w+64) -> 32 f32x2 W_hh registers.
//   warp 0: tree psum reduce, fast gates, h store; counter barrier per step.
//   After the loop, CTA 0 computes the fc epilogue (fold; visibility via the
//   final barrier's acquire).
// ===========================================================================
__global__ void __launch_bounds__(512, 1) lstm_rec_kernel(
    const float* __restrict__ W_hh,   // [4096,1024]
    const float* __restrict__ c1,     // [1024]
    const float* __restrict__ b_hh,   // [4096]
    const float* __restrict__ fc_w,   // [32,1024]
    const float* __restrict__ fc_b,   // [32]
    float* __restrict__ out,          // d_out
    int writeHC)
{
    __shared__ __align__(16) float hsm[HID];
    __shared__ float psum[16][33];

    const int tid = threadIdx.x;
    const int bid = blockIdx.x;
    const int w = tid >> 5;
    const int l = tid & 31;
    const int u = l >> 2;
    const int g = l & 3;
    const int gate_row = g * HID + bid * UPB + u;

    // ---- W_hh slab into registers: 32 f32x2 per thread ----
    unsigned long long wreg[32];
    {
        const float* wp = W_hh + (size_t)gate_row * HID + w * 64;
#pragma unroll
        for (int k = 0; k < 32; k++)
            wreg[k] = *(const unsigned long long*)(wp + 2 * k);
    }

    // ---- warp-0 per-lane state ----
    float bias = 0.f, xg = 0.f, c = 0.f;
    if (w == 0) {
        bias = b_hh[gate_row];
        xg   = __ldg(g_xg + gate_row);       // row t=0
        if (g == 0) c = c1[bid * UPB + u];
    }
    __syncthreads();

    for (int t = 0; t < WINDOW; t++) {
        const int p = t & 1;

        // ---- broadcast h into SMEM (L2-only loads) ----
        if (tid < 256)
            ((float4*)hsm)[tid] = __ldcg(((const float4*)g_h[p]) + tid);
        __syncthreads();

        // ---- 64-col partial dot, 4 accumulators to shorten the chain ----
        unsigned long long a0 = 0ull, a1 = 0ull, a2 = 0ull, a3 = 0ull;
        const unsigned long long* hp = (const unsigned long long*)(hsm + w * 64);
#pragma unroll
        for (int k = 0; k < 8; k++) {
            fma2(a0, wreg[4 * k + 0], hp[4 * k + 0]);
            fma2(a1, wreg[4 * k + 1], hp[4 * k + 1]);
            fma2(a2, wreg[4 * k + 2], hp[4 * k + 2]);
            fma2(a3, wreg[4 * k + 3], hp[4 * k + 3]);
        }
        {
            unsigned int x0, y0, x1, y1, x2, y2, x3, y3;
            asm("mov.b64 {%0, %1}, %2;" : "=r"(x0), "=r"(y0) : "l"(a0));
            asm("mov.b64 {%0, %1}, %2;" : "=r"(x1), "=r"(y1) : "l"(a1));
            asm("mov.b64 {%0, %1}, %2;" : "=r"(x2), "=r"(y2) : "l"(a2));
            asm("mov.b64 {%0, %1}, %2;" : "=r"(x3), "=r"(y3) : "l"(a3));
            float s01 = (__uint_as_float(x0) + __uint_as_float(y0))
                      + (__uint_as_float(x1) + __uint_as_float(y1));
            float s23 = (__uint_as_float(x2) + __uint_as_float(y2))
                      + (__uint_as_float(x3) + __uint_as_float(y3));
            psum[w][l] = s01 + s23;
        }
        __syncthreads();

        // ---- warp 0: tree reduce, fast gates, h store ----
        if (w == 0) {
            float v0 = psum[0][l]  + psum[1][l];
            float v1 = psum[2][l]  + psum[3][l];
            float v2 = psum[4][l]  + psum[5][l];
            float v3 = psum[6][l]  + psum[7][l];
            float v4 = psum[8][l]  + psum[9][l];
            float v5 = psum[10][l] + psum[11][l];
            float v6 = psum[12][l] + psum[13][l];
            float v7 = psum[14][l] + psum[15][l];
            float pre = (((v0 + v1) + (v2 + v3)) + ((v4 + v5) + (v6 + v7)))
                      + (xg + bias);

            float a = (g == 2) ? tanh_fast(pre) : sig_fast(pre);
            int base = l & ~3;
            float fg = __shfl_sync(0xffffffffu, a, base + 1);
            float gb = __shfl_sync(0xffffffffu, a, base + 2);
            float og = __shfl_sync(0xffffffffu, a, base + 3);
            if (g == 0) {
                c = fg * c + a * gb;
                float hn = og * tanh_fast(c);
                int jj = bid * UPB + u;
                g_h[p ^ 1][jj] = hn;
                if (writeHC && t == 1023) {          // STRIDE-1
                    out[METRIC + jj] = hn;
                    out[METRIC + HID + jj] = c;
                }
            }
            // prefetch next step's xg (hides L2 latency under the barrier)
            if (t + 1 < WINDOW)
                xg = __ldg(g_xg + (size_t)(t + 1) * GATE4 + gate_row);
        }
        __syncthreads();

        // ---- grid barrier: release-RED arrival + tid0 acquire poll ----
        if (tid == 0) {
            red_release_add1(&g_cnt);
            const int target = (t + 1) * NCTA;
            while (ld_acquire(&g_cnt) < target) { }
        }
        __syncthreads();
    }

    // ---- fc epilogue folded in: CTA 0 only, h_fin = g_h[0] ----
    // Visibility: this CTA's final acquire poll observed all 128 arrivals,
    // each release-ordered after its CTA's h stores.
    if (bid == 0) {
#pragma unroll
        for (int half = 0; half < 2; half++) {
            const int m = 2 * w + half;              // metric 0..31
            const float4* wv = (const float4*)(fc_w + (size_t)m * HID);
            float s = 0.f;
#pragma unroll
            for (int jj = 0; jj < 8; jj++) {
                float4 a = __ldcg(((const float4*)g_h[0]) + l + 32 * jj);
                float4 b = __ldg(wv + l + 32 * jj);
                s += a.x * b.x + a.y * b.y + a.z * b.z + a.w * b.w;
            }
#pragma unroll
            for (int off = 16; off; off >>= 1)
                s += __shfl_xor_sync(0xffffffffu, s, off);
            if (l == 0) out[m] = tanhf(s + fc_b[m]);
        }
    }
}

// ===========================================================================
// launch — exactly 3 launches per call (gemm, init, lstm):
// ncu -s 5 -c 1 lands on call 2's lstm_rec_kernel.
// ===========================================================================
extern "C" void kernel_launch(void* const* d_in, const int* in_sizes, int n_in,
                              void* d_out, int out_size) {
    const float* inp  = (const float*)d_in[0];
    const float* h1   = (const float*)d_in[1];
    const float* c1   = (const float*)d_in[2];
    const float* W_ih = (const float*)d_in[3];
    const float* W_hh = (const float*)d_in[4];
    const float* b_ih = (const float*)d_in[5];
    const float* b_hh = (const float*)d_in[6];
    const float* fc_w = (const float*)d_in[7];
    const float* fc_b = (const float*)d_in[8];
    float* out = (float*)d_out;

    int writeHC = (out_size >= METRIC + 2 * HID) ? 1 : 0;

    float* xg_ptr = nullptr;
    cudaGetSymbolAddress((void**)&xg_ptr, g_xg);

    // Phase 1: xg GEMM
    dim3 ggrid(GATE4 / BN, WINDOW / BM);
    gemm_xg_kernel<<<ggrid, 256>>>(inp, W_ih, b_ih, xg_ptr);

    // Phase 1b: init h buffer + barrier counter
    init_kernel<<<1, HID>>>(h1);

    // Phase 2: persistent recurrence + folded fc epilogue
    lstm_rec_kernel<<<NCTA, 512>>>(W_hh, c1, b_hh, fc_w, fc_b, out, writeHC);
}

// round 14
// speedup vs baseline: 1.7153x; 1.4671x over previous
#include <cuda_runtime.h>
#include <cuda_bf16.h>
#include <cstdint>

// ---------------------------------------------------------------------------
// OnlineLSTM (round 14 = round 11 compute verbatim + fast activations + fc fold)
//   Phase 1: xg = inp @ W_ih^T + b_ih  (proven FFMA2 SGEMM, unchanged)
//   Phase 2: persistent recurrence, W_hh in registers (SINGLE accumulator —
//            R13's 4-acc/tree-reduce variant blew the 128-reg/thread cap from
//            __launch_bounds__(512,1) and spilled wreg to local), counter
//            barrier, fc folded into CTA-0 tail.
//   3 launches/call -> ncu (-s 5 -c 1) lands on call 2's lstm_rec_kernel.
// ---------------------------------------------------------------------------

#define WINDOW  2048
#define ISZ     4096
#define HID     1024
#define GATE4   4096      // 4*HID
#define METRIC  32
#define NCTA    128       // persistent CTAs
#define UPB     8         // hidden units per CTA (NCTA*UPB = HID)

// Scratch (no cudaMalloc allowed)
__device__ float g_xg[WINDOW * GATE4];          // 32 MB
__device__ float g_h[2][HID];
__device__ int   g_cnt;                          // monotonic barrier counter

// ===========================================================================
// GEMM: C[t][r] = sum_k inp[t][k] * W_ih[r][k] + b_ih[r]   (round-3 verbatim)
// ===========================================================================
#define BM 128
#define BN 128
#define BK 8
#define LDT (BM + 4)

__device__ __forceinline__ unsigned long long dup_f32x2(float a) {
    unsigned long long r;
    unsigned int ai = __float_as_uint(a);
    asm("mov.b64 %0, {%1, %1};" : "=l"(r) : "r"(ai));
    return r;
}
__device__ __forceinline__ void fma2(unsigned long long& acc,
                                     unsigned long long a,
                                     unsigned long long b) {
    asm("fma.rn.f32x2 %0, %1, %2, %0;" : "+l"(acc) : "l"(a), "l"(b));
}

__global__ void __launch_bounds__(256, 2) gemm_xg_kernel(
    const float* __restrict__ A,      // inp [2048,4096]
    const float* __restrict__ B,      // W_ih [4096,4096]
    const float* __restrict__ bias,   // b_ih [4096]
    float* __restrict__ C)            // g_xg [2048,4096]
{
    __shared__ __align__(16) float As[BK][LDT];
    __shared__ __align__(16) float Bs[BK][LDT];

    const int tid = threadIdx.x;
    const int bm = blockIdx.y * BM;
    const int bn = blockIdx.x * BN;

    const int lr = tid >> 1;
    const int lk = (tid & 1) * 4;
    const float* Aptr = A + (size_t)(bm + lr) * ISZ + lk;
    const float* Bptr = B + (size_t)(bn + lr) * ISZ + lk;

    const int tx = tid & 15;
    const int ty = tid >> 4;

    unsigned long long acc2[8][4];
#pragma unroll
    for (int i = 0; i < 8; i++)
#pragma unroll
        for (int j = 0; j < 4; j++) acc2[i][j] = 0ull;

    float4 av = *(const float4*)(Aptr);
    float4 bv = *(const float4*)(Bptr);

    for (int k0 = 0; k0 < ISZ; k0 += BK) {
        __syncthreads();
        As[lk + 0][lr] = av.x; As[lk + 1][lr] = av.y;
        As[lk + 2][lr] = av.z; As[lk + 3][lr] = av.w;
        Bs[lk + 0][lr] = bv.x; Bs[lk + 1][lr] = bv.y;
        Bs[lk + 2][lr] = bv.z; Bs[lk + 3][lr] = bv.w;
        __syncthreads();

        if (k0 + BK < ISZ) {
            av = *(const float4*)(Aptr + k0 + BK);
            bv = *(const float4*)(Bptr + k0 + BK);
        }

#pragma unroll
        for (int kk = 0; kk < BK; kk++) {
            float4 a0 = *(const float4*)&As[kk][ty * 8];
            float4 a1 = *(const float4*)&As[kk][ty * 8 + 4];
            ulonglong2 bq0 = *(const ulonglong2*)&Bs[kk][tx * 8];
            ulonglong2 bq1 = *(const ulonglong2*)&Bs[kk][tx * 8 + 4];
            unsigned long long b2[4] = {bq0.x, bq0.y, bq1.x, bq1.y};
            float a[8] = {a0.x, a0.y, a0.z, a0.w, a1.x, a1.y, a1.z, a1.w};
#pragma unroll
            for (int i = 0; i < 8; i++) {
                unsigned long long ad = dup_f32x2(a[i]);
#pragma unroll
                for (int j = 0; j < 4; j++) fma2(acc2[i][j], ad, b2[j]);
            }
        }
    }

    float bcol[8];
#pragma unroll
    for (int j = 0; j < 8; j++) bcol[j] = bias[bn + tx * 8 + j];

#pragma unroll
    for (int i = 0; i < 8; i++) {
        float* crow = C + (size_t)(bm + ty * 8 + i) * GATE4 + bn + tx * 8;
#pragma unroll
        for (int j = 0; j < 4; j++) {
            unsigned int lo, hi;
            asm("mov.b64 {%0, %1}, %2;" : "=r"(lo), "=r"(hi) : "l"(acc2[i][j]));
            crow[2 * j]     = __uint_as_float(lo) + bcol[2 * j];
            crow[2 * j + 1] = __uint_as_float(hi) + bcol[2 * j + 1];
        }
    }
}

// ===========================================================================
// Init: reset barrier counter, seed h buffer (proven)
// ===========================================================================
__global__ void init_kernel(const float* __restrict__ h1) {
    int i = threadIdx.x;   // 1024 threads
    if (i == 0) g_cnt = 0;
    g_h[0][i] = h1[i];
}

// ===========================================================================
// Barrier primitives (proven)
// ===========================================================================
__device__ __forceinline__ void red_release_add1(int* p) {
    asm volatile("red.release.gpu.global.add.s32 [%0], 1;" :: "l"(p) : "memory");
}
__device__ __forceinline__ int ld_acquire(const int* p) {
    int v;
    asm volatile("ld.acquire.gpu.global.b32 %0, [%1];" : "=r"(v) : "l"(p) : "memory");
    return v;
}

// Fast saturating activations (exact at +-inf; rel err ~1e-6; fewer regs
// than the tanhf call sequence)
__device__ __forceinline__ float sig_fast(float x) {
    return __fdividef(1.0f, 1.0f + __expf(-x));
}
__device__ __forceinline__ float tanh_fast(float x) {
    return 1.0f - __fdividef(2.0f, __expf(2.0f * x) + 1.0f);
}

// ===========================================================================
// Persistent LSTM recurrence — ROUND-11 COMPUTE VERBATIM (single accumulator,
// serial psum reduce: the register footprint that fits under the 128-reg cap
// without spilling wreg). Counter barrier per step. CTA-0 fc tail.
// ===========================================================================
__global__ void __launch_bounds__(512, 1) lstm_rec_kernel(
    const float* __restrict__ W_hh,   // [4096,1024]
    const float* __restrict__ c1,     // [1024]
    const float* __restrict__ b_hh,   // [4096]
    const float* __restrict__ fc_w,   // [32,1024]
    const float* __restrict__ fc_b,   // [32]
    float* __restrict__ out,          // d_out
    int writeHC)
{
    __shared__ __align__(16) float hsm[HID];
    __shared__ float psum[16][33];

    const int tid = threadIdx.x;
    const int bid = blockIdx.x;
    const int w = tid >> 5;
    const int l = tid & 31;
    const int u = l >> 2;
    const int g = l & 3;
    const int gate_row = g * HID + bid * UPB + u;

    // ---- W_hh slab into registers: 32 f32x2 per thread ----
    unsigned long long wreg[32];
    {
        const float* wp = W_hh + (size_t)gate_row * HID + w * 64;
#pragma unroll
        for (int k = 0; k < 32; k++)
            wreg[k] = *(const unsigned long long*)(wp + 2 * k);
    }

    // ---- warp-0 per-lane state ----
    float bias = 0.f, xg = 0.f, c = 0.f;
    if (w == 0) {
        bias = b_hh[gate_row];
        xg   = __ldg(g_xg + gate_row);       // row t=0
        if (g == 0) c = c1[bid * UPB + u];
    }
    __syncthreads();

    for (int t = 0; t < WINDOW; t++) {
        const int p = t & 1;

        // ---- broadcast h into SMEM (L2-only loads) ----
        if (tid < 256)
            ((float4*)hsm)[tid] = __ldcg(((const float4*)g_h[p]) + tid);
        __syncthreads();

        // ---- 64-col partial dot: single accumulator (R11 verbatim) ----
        unsigned long long acc = 0ull;
        const unsigned long long* hp = (const unsigned long long*)(hsm + w * 64);
#pragma unroll
        for (int k = 0; k < 32; k++) fma2(acc, wreg[k], hp[k]);
        {
            unsigned int lo, hi;
            asm("mov.b64 {%0, %1}, %2;" : "=r"(lo), "=r"(hi) : "l"(acc));
            psum[w][l] = __uint_as_float(lo) + __uint_as_float(hi);
        }
        __syncthreads();

        // ---- warp 0: serial reduce (R11 verbatim), fast gates, h store ----
        if (w == 0) {
            float pre = xg + bias;
#pragma unroll
            for (int q = 0; q < 16; q++) pre += psum[q][l];

            float a = (g == 2) ? tanh_fast(pre) : sig_fast(pre);
            int base = l & ~3;
            float fg = __shfl_sync(0xffffffffu, a, base + 1);
            float gb = __shfl_sync(0xffffffffu, a, base + 2);
            float og = __shfl_sync(0xffffffffu, a, base + 3);
            if (g == 0) {
                c = fg * c + a * gb;
                float hn = og * tanh_fast(c);
                int jj = bid * UPB + u;
                g_h[p ^ 1][jj] = hn;
                if (writeHC && t == 1023) {          // STRIDE-1
                    out[METRIC + jj] = hn;
                    out[METRIC + HID + jj] = c;
                }
            }
            // prefetch next step's xg (hides L2 latency under the barrier)
            if (t + 1 < WINDOW)
                xg = __ldg(g_xg + (size_t)(t + 1) * GATE4 + gate_row);
        }
        __syncthreads();

        // ---- grid barrier: release-RED arrival + tid0 acquire poll ----
        if (tid == 0) {
            red_release_add1(&g_cnt);
            const int target = (t + 1) * NCTA;
            while (ld_acquire(&g_cnt) < target) { }
        }
        __syncthreads();
    }

    // ---- fc epilogue folded in: CTA 0 only, h_fin = g_h[0] ----
    // Visibility: the final acquire poll observed all 128 release-ordered
    // arrivals, each ordered after that CTA's h stores.
    if (bid == 0) {
        for (int half = 0; half < 2; half++) {
            const int m = 2 * w + half;              // metric 0..31
            const float4* wv = (const float4*)(fc_w + (size_t)m * HID);
            float s = 0.f;
#pragma unroll
            for (int jj = 0; jj < 8; jj++) {
                float4 a = __ldcg(((const float4*)g_h[0]) + l + 32 * jj);
                float4 b = __ldg(wv + l + 32 * jj);
                s += a.x * b.x + a.y * b.y + a.z * b.z + a.w * b.w;
            }
#pragma unroll
            for (int off = 16; off; off >>= 1)
                s += __shfl_xor_sync(0xffffffffu, s, off);
            if (l == 0) out[m] = tanhf(s + fc_b[m]);
        }
    }
}

// ===========================================================================
// launch — exactly 3 launches per call (gemm, init, lstm)
// ===========================================================================
extern "C" void kernel_launch(void* const* d_in, const int* in_sizes, int n_in,
                              void* d_out, int out_size) {
    const float* inp  = (const float*)d_in[0];
    const float* h1   = (const float*)d_in[1];
    const float* c1   = (const float*)d_in[2];
    const float* W_ih = (const float*)d_in[3];
    const float* W_hh = (const float*)d_in[4];
    const float* b_ih = (const float*)d_in[5];
    const float* b_hh = (const float*)d_in[6];
    const float* fc_w = (const float*)d_in[7];
    const float* fc_b = (const float*)d_in[8];
    float* out = (float*)d_out;

    int writeHC = (out_size >= METRIC + 2 * HID) ? 1 : 0;

    float* xg_ptr = nullptr;
    cudaGetSymbolAddress((void**)&xg_ptr, g_xg);

    // Phase 1: xg GEMM
    dim3 ggrid(GATE4 / BN, WINDOW / BM);
    gemm_xg_kernel<<<ggrid, 256>>>(inp, W_ih, b_ih, xg_ptr);

    // Phase 1b: init h buffer + barrier counter
    init_kernel<<<1, HID>>>(h1);

    // Phase 2: persistent recurrence + folded fc epilogue
    lstm_rec_kernel<<<NCTA, 512>>>(W_hh, c1, b_hh, fc_w, fc_b, out, writeHC);
}

// round 15
// speedup vs baseline: 1.7670x; 1.0301x over previous
#include <cuda_runtime.h>
#include <cuda_bf16.h>
#include <cstdint>

// ---------------------------------------------------------------------------
// OnlineLSTM (round 15 = round 14 + GEMM double-buffer + 2-acc dot +
//             per-warp hsm slab load):
//   Phase 1: xg = inp @ W_ih^T + b_ih  (FFMA2 SGEMM, SMEM ping-pong)
//   Phase 2: persistent recurrence, W_hh in registers, counter barrier,
//            fc folded into CTA-0 tail.
// ---------------------------------------------------------------------------

#define WINDOW  2048
#define ISZ     4096
#define HID     1024
#define GATE4   4096      // 4*HID
#define METRIC  32
#define NCTA    128       // persistent CTAs
#define UPB     8         // hidden units per CTA (NCTA*UPB = HID)

// Scratch (no cudaMalloc allowed)
__device__ float g_xg[WINDOW * GATE4];          // 32 MB
__device__ float g_h[2][HID];
__device__ int   g_cnt;                          // monotonic barrier counter

// ===========================================================================
// GEMM: C[t][r] = sum_k inp[t][k] * W_ih[r][k] + b_ih[r]
// 128x128 tile, BK=8, 256 threads, 8x8 micro-tile via fma.rn.f32x2.
// Round 15: double-buffered SMEM -> ONE __syncthreads per K-tile.
// ===========================================================================
#define BM 128
#define BN 128
#define BK 8
#define LDT (BM + 4)

__device__ __forceinline__ unsigned long long dup_f32x2(float a) {
    unsigned long long r;
    unsigned int ai = __float_as_uint(a);
    asm("mov.b64 %0, {%1, %1};" : "=l"(r) : "r"(ai));
    return r;
}
__device__ __forceinline__ void fma2(unsigned long long& acc,
                                     unsigned long long a,
                                     unsigned long long b) {
    asm("fma.rn.f32x2 %0, %1, %2, %0;" : "+l"(acc) : "l"(a), "l"(b));
}

__global__ void __launch_bounds__(256, 2) gemm_xg_kernel(
    const float* __restrict__ A,      // inp [2048,4096]
    const float* __restrict__ B,      // W_ih [4096,4096]
    const float* __restrict__ bias,   // b_ih [4096]
    float* __restrict__ C)            // g_xg [2048,4096]
{
    __shared__ __align__(16) float As[2][BK][LDT];
    __shared__ __align__(16) float Bs[2][BK][LDT];

    const int tid = threadIdx.x;
    const int bm = blockIdx.y * BM;
    const int bn = blockIdx.x * BN;

    const int lr = tid >> 1;          // 0..127 row within tile
    const int lk = (tid & 1) * 4;     // 0 or 4
    const float* Aptr = A + (size_t)(bm + lr) * ISZ + lk;
    const float* Bptr = B + (size_t)(bn + lr) * ISZ + lk;

    const int tx = tid & 15;          // n dim
    const int ty = tid >> 4;          // m dim

    unsigned long long acc2[8][4];
#pragma unroll
    for (int i = 0; i < 8; i++)
#pragma unroll
        for (int j = 0; j < 4; j++) acc2[i][j] = 0ull;

    // prologue: fill buffer 0
    {
        float4 av = *(const float4*)(Aptr);
        float4 bv = *(const float4*)(Bptr);
        As[0][lk + 0][lr] = av.x; As[0][lk + 1][lr] = av.y;
        As[0][lk + 2][lr] = av.z; As[0][lk + 3][lr] = av.w;
        Bs[0][lk + 0][lr] = bv.x; Bs[0][lk + 1][lr] = bv.y;
        Bs[0][lk + 2][lr] = bv.z; Bs[0][lk + 3][lr] = bv.w;
    }
    __syncthreads();

    for (int k0 = 0; k0 < ISZ; k0 += BK) {
        const int cur = (k0 >> 3) & 1;
        const bool more = (k0 + BK < ISZ);

        // prefetch next tile from global (issued before compute)
        float4 avn, bvn;
        if (more) {
            avn = *(const float4*)(Aptr + k0 + BK);
            bvn = *(const float4*)(Bptr + k0 + BK);
        }

        // compute on buffer `cur`
#pragma unroll
        for (int kk = 0; kk < BK; kk++) {
            float4 a0 = *(const float4*)&As[cur][kk][ty * 8];
            float4 a1 = *(const float4*)&As[cur][kk][ty * 8 + 4];
            ulonglong2 bq0 = *(const ulonglong2*)&Bs[cur][kk][tx * 8];
            ulonglong2 bq1 = *(const ulonglong2*)&Bs[cur][kk][tx * 8 + 4];
            unsigned long long b2[4] = {bq0.x, bq0.y, bq1.x, bq1.y};
            float a[8] = {a0.x, a0.y, a0.z, a0.w, a1.x, a1.y, a1.z, a1.w};
#pragma unroll
            for (int i = 0; i < 8; i++) {
                unsigned long long ad = dup_f32x2(a[i]);
#pragma unroll
                for (int j = 0; j < 4; j++) fma2(acc2[i][j], ad, b2[j]);
            }
        }

        // stage next tile into the other buffer; single sync per K-tile
        if (more) {
            const int nxt = cur ^ 1;
            As[nxt][lk + 0][lr] = avn.x; As[nxt][lk + 1][lr] = avn.y;
            As[nxt][lk + 2][lr] = avn.z; As[nxt][lk + 3][lr] = avn.w;
            Bs[nxt][lk + 0][lr] = bvn.x; Bs[nxt][lk + 1][lr] = bvn.y;
            Bs[nxt][lk + 2][lr] = bvn.z; Bs[nxt][lk + 3][lr] = bvn.w;
            __syncthreads();
        }
    }

    float bcol[8];
#pragma unroll
    for (int j = 0; j < 8; j++) bcol[j] = bias[bn + tx * 8 + j];

#pragma unroll
    for (int i = 0; i < 8; i++) {
        float* crow = C + (size_t)(bm + ty * 8 + i) * GATE4 + bn + tx * 8;
#pragma unroll
        for (int j = 0; j < 4; j++) {
            unsigned int lo, hi;
            asm("mov.b64 {%0, %1}, %2;" : "=r"(lo), "=r"(hi) : "l"(acc2[i][j]));
            crow[2 * j]     = __uint_as_float(lo) + bcol[2 * j];
            crow[2 * j + 1] = __uint_as_float(hi) + bcol[2 * j + 1];
        }
    }
}

// ===========================================================================
// Init: reset barrier counter, seed h buffer (proven)
// ===========================================================================
__global__ void init_kernel(const float* __restrict__ h1) {
    int i = threadIdx.x;   // 1024 threads
    if (i == 0) g_cnt = 0;
    g_h[0][i] = h1[i];
}

// ===========================================================================
// Barrier primitives (proven)
// ===========================================================================
__device__ __forceinline__ void red_release_add1(int* p) {
    asm volatile("red.release.gpu.global.add.s32 [%0], 1;" :: "l"(p) : "memory");
}
__device__ __forceinline__ int ld_acquire(const int* p) {
    int v;
    asm volatile("ld.acquire.gpu.global.b32 %0, [%1];" : "=r"(v) : "l"(p) : "memory");
    return v;
}

// Fast saturating activations (exact at +-inf; rel err ~1e-6)
__device__ __forceinline__ float sig_fast(float x) {
    return __fdividef(1.0f, 1.0f + __expf(-x));
}
__device__ __forceinline__ float tanh_fast(float x) {
    return 1.0f - __fdividef(2.0f, __expf(2.0f * x) + 1.0f);
}

// ===========================================================================
// Persistent LSTM recurrence. 128 CTAs x 512 threads; W_hh in registers;
// counter barrier per step; CTA-0 fc tail.
// Round-15 trims vs R14: (a) each warp self-loads its 64-float h slab
// (drops one __syncthreads), (b) 2-accumulator dot (+2 regs only).
// ===========================================================================
__global__ void __launch_bounds__(512, 1) lstm_rec_kernel(
    const float* __restrict__ W_hh,   // [4096,1024]
    const float* __restrict__ c1,     // [1024]
    const float* __restrict__ b_hh,   // [4096]
    const float* __restrict__ fc_w,   // [32,1024]
    const float* __restrict__ fc_b,   // [32]
    float* __restrict__ out,          // d_out
    int writeHC)
{
    __shared__ __align__(16) float hsm[HID];
    __shared__ float psum[16][33];

    const int tid = threadIdx.x;
    const int bid = blockIdx.x;
    const int w = tid >> 5;
    const int l = tid & 31;
    const int u = l >> 2;
    const int g = l & 3;
    const int gate_row = g * HID + bid * UPB + u;

    // ---- W_hh slab into registers: 32 f32x2 per thread ----
    unsigned long long wreg[32];
    {
        const float* wp = W_hh + (size_t)gate_row * HID + w * 64;
#pragma unroll
        for (int k = 0; k < 32; k++)
            wreg[k] = *(const unsigned long long*)(wp + 2 * k);
    }

    // ---- warp-0 per-lane state ----
    float bias = 0.f, xg = 0.f, c = 0.f;
    if (w == 0) {
        bias = b_hh[gate_row];
        xg   = __ldg(g_xg + gate_row);       // row t=0
        if (g == 0) c = c1[bid * UPB + u];
    }
    __syncthreads();

    for (int t = 0; t < WINDOW; t++) {
        const int p = t & 1;

        // ---- each warp loads its OWN 64-float h slab (no block sync) ----
        if (l < 16)
            ((float4*)(hsm + w * 64))[l] =
                __ldcg(((const float4*)g_h[p]) + w * 16 + l);
        __syncwarp();

        // ---- 64-col partial dot: 2 accumulators (chain halved, +2 regs) ----
        unsigned long long acc0 = 0ull, acc1 = 0ull;
        const unsigned long long* hp = (const unsigned long long*)(hsm + w * 64);
#pragma unroll
        for (int k = 0; k < 16; k++) {
            fma2(acc0, wreg[2 * k],     hp[2 * k]);
            fma2(acc1, wreg[2 * k + 1], hp[2 * k + 1]);
        }
        {
            unsigned int x0, y0, x1, y1;
            asm("mov.b64 {%0, %1}, %2;" : "=r"(x0), "=r"(y0) : "l"(acc0));
            asm("mov.b64 {%0, %1}, %2;" : "=r"(x1), "=r"(y1) : "l"(acc1));
            psum[w][l] = (__uint_as_float(x0) + __uint_as_float(y0))
                       + (__uint_as_float(x1) + __uint_as_float(y1));
        }
        __syncthreads();

        // ---- warp 0: serial reduce, fast gates, h store ----
        if (w == 0) {
            float pre = xg + bias;
#pragma unroll
            for (int q = 0; q < 16; q++) pre += psum[q][l];

            float a = (g == 2) ? tanh_fast(pre) : sig_fast(pre);
            int base = l & ~3;
            float fg = __shfl_sync(0xffffffffu, a, base + 1);
            float gb = __shfl_sync(0xffffffffu, a, base + 2);
            float og = __shfl_sync(0xffffffffu, a, base + 3);
            if (g == 0) {
                c = fg * c + a * gb;
                float hn = og * tanh_fast(c);
                int jj = bid * UPB + u;
                g_h[p ^ 1][jj] = hn;
                if (writeHC && t == 1023) {          // STRIDE-1
                    out[METRIC + jj] = hn;
                    out[METRIC + HID + jj] = c;
                }
            }
            // prefetch next step's xg (hides L2 latency under the barrier)
            if (t + 1 < WINDOW)
                xg = __ldg(g_xg + (size_t)(t + 1) * GATE4 + gate_row);
        }
        __syncthreads();

        // ---- grid barrier: release-RED arrival + tid0 acquire poll ----
        if (tid == 0) {
            red_release_add1(&g_cnt);
            const int target = (t + 1) * NCTA;
            while (ld_acquire(&g_cnt) < target) { }
        }
        __syncthreads();
    }

    // ---- fc epilogue folded in: CTA 0 only, h_fin = g_h[0] ----
    if (bid == 0) {
        for (int half = 0; half < 2; half++) {
            const int m = 2 * w + half;              // metric 0..31
            const float4* wv = (const float4*)(fc_w + (size_t)m * HID);
            float s = 0.f;
#pragma unroll
            for (int jj = 0; jj < 8; jj++) {
                float4 a = __ldcg(((const float4*)g_h[0]) + l + 32 * jj);
                float4 b = __ldg(wv + l + 32 * jj);
                s += a.x * b.x + a.y * b.y + a.z * b.z + a.w * b.w;
            }
#pragma unroll
            for (int off = 16; off; off >>= 1)
                s += __shfl_xor_sync(0xffffffffu, s, off);
            if (l == 0) out[m] = tanhf(s + fc_b[m]);
        }
    }
}

// ===========================================================================
// launch — exactly 3 launches per call (gemm, init, lstm)
// ===========================================================================
extern "C" void kernel_launch(void* const* d_in, const int* in_sizes, int n_in,
                              void* d_out, int out_size) {
    const float* inp  = (const float*)d_in[0];
    const float* h1   = (const float*)d_in[1];
    const float* c1   = (const float*)d_in[2];
    const float* W_ih = (const float*)d_in[3];
    const float* W_hh = (const float*)d_in[4];
    const float* b_ih = (const float*)d_in[5];
    const float* b_hh = (const float*)d_in[6];
    const float* fc_w = (const float*)d_in[7];
    const float* fc_b = (const float*)d_in[8];
    float* out = (float*)d_out;

    int writeHC = (out_size >= METRIC + 2 * HID) ? 1 : 0;

    float* xg_ptr = nullptr;
    cudaGetSymbolAddress((void**)&xg_ptr, g_xg);

    // Phase 1: xg GEMM (double-buffered)
    dim3 ggrid(GATE4 / BN, WINDOW / BM);
    gemm_xg_kernel<<<ggrid, 256>>>(inp, W_ih, b_ih, xg_ptr);

    // Phase 1b: init h buffer + barrier counter
    init_kernel<<<1, HID>>>(h1);

    // Phase 2: persistent recurrence + folded fc epilogue
    lstm_rec_kernel<<<NCTA, 512>>>(W_hh, c1, b_hh, fc_w, fc_b, out, writeHC);
}